// round 6
// baseline (speedup 1.0000x reference)
#include <cuda_runtime.h>
#include <cuda_bf16.h>

// ---------------- static scratch (no runtime allocation allowed) ----------------
#define NMAX 50048
#define EMAX 1664000
#define GMAXG 512

__device__ float g_feat[(size_t)NMAX * 245];
__device__ float g_h0[(size_t)NMAX * 128];
__device__ float g_h1[(size_t)NMAX * 128];
__device__ float g_h2[(size_t)NMAX * 128];
__device__ float g_deg[NMAX];
__device__ float g_dinv[NMAX];
__device__ int   g_indeg[NMAX];
__device__ int   g_off[NMAX + 1];
__device__ int   g_cur[NMAX];
__device__ int2  g_edge[EMAX];
__device__ float g_bnsum[128];
__device__ float g_bnsq[128];
__device__ float g_ab[256];
__device__ float g_gsum[GMAXG * 128];
__device__ float g_gcnt[GMAXG];

// ---------------- zero init ----------------
__global__ void k_zero(int n) {
    int i = blockIdx.x * blockDim.x + threadIdx.x;
    if (i < n) { g_deg[i] = 0.f; g_indeg[i] = 0; }
    if (i < 128) { g_bnsum[i] = 0.f; g_bnsq[i] = 0.f; }
    if (i < GMAXG * 128) g_gsum[i] = 0.f;
    if (i < GMAXG) g_gcnt[i] = 0.f;
}

// ---------------- CNN encoder: fully float4-vectorized smem, 6 nodes / block ----
// rows padded to 20 floats (16B-aligned); weights transposed oc-innermost.
// smem floats: w1t[224] | w2t[1608] | xs[6*1140] | c1s[6*2720]
#define CNN_NPB 6
#define SM_W1   0
#define SM_W2   224
#define SM_XS   (224 + 1608)
#define SM_C1S  (SM_XS + CNN_NPB * 1140)
#define CNN_SMEM_FLOATS (SM_C1S + CNN_NPB * 2720)

__global__ __launch_bounds__(256, 2) void k_cnn(
    const float* __restrict__ x,
    const float* __restrict__ c1w, const float* __restrict__ c1b,
    const float* __restrict__ c2w, const float* __restrict__ c2b, int n)
{
    extern __shared__ float sm[];
    float* w1t = sm + SM_W1;    // [27][8] oc-innermost, +8 bias at [216..223]
    float* w2t = sm + SM_W2;    // [200][8] oc-innermost (oc 5..7 zero), +5 bias at [1600..]
    float* xs  = sm + SM_XS;    // per node: [3 ic][19 y][20]
    float* c1s = sm + SM_C1S;   // per node: [8 oc][17 y][20]

    int t = threadIdx.x;
    int node0 = blockIdx.x * CNN_NPB;
    int nLocal = n - node0; if (nLocal > CNN_NPB) nLocal = CNN_NPB;
    if (nLocal <= 0) return;

    // transpose conv1 weights: w1t[(ic*3+ky)*3+kx][oc]
    for (int i = t; i < 216; i += 256) {
        int oc = i / 27, r = i - oc * 27;
        w1t[r * 8 + oc] = c1w[i];
    }
    if (t < 8) w1t[216 + t] = c1b[t];
    // transpose conv2 weights: w2t[(ic*5+ky)*5+kx][oc], oc 5..7 = 0
    for (int i = t; i < 1600; i += 256) {
        int oc = i & 7, idx = i >> 3;
        int kx = idx % 5, ky = (idx / 5) % 5, ic = idx / 25;
        w2t[i] = (oc < 5) ? c2w[((oc * 8 + ic) * 5 + ky) * 5 + kx] : 0.f;
    }
    if (t < 5) w2t[1600 + t] = c2b[t];

    // load x with row padding 19 -> 20
    int totx = nLocal * 1083;
    const float* xp = x + (size_t)node0 * 1083;
    for (int i = t; i < totx; i += 256) {
        int nd = i / 1083, rem = i - nd * 1083;
        int row = rem / 19, col = rem - row * 19;
        xs[nd * 1140 + row * 20 + col] = xp[i];
    }
    __syncthreads();

    // ---- conv1: task = (node, oy, ocg of 4); all smem ops are float4 ----
    int tasks1 = nLocal * 34;
    for (int tt = t; tt < tasks1; tt += 256) {
        int nd  = tt / 34;
        int rid = tt - nd * 34;
        int ocg = rid / 17;
        int oy  = rid - ocg * 17;
        const float* xb = xs + nd * 1140;

        float acc[4][17];
        {
            float4 bq = ((const float4*)(w1t + 216))[ocg];
            float bb[4] = {bq.x, bq.y, bq.z, bq.w};
#pragma unroll
            for (int o = 0; o < 4; o++)
#pragma unroll
                for (int ox = 0; ox < 17; ox++) acc[o][ox] = bb[o];
        }
#pragma unroll
        for (int ic = 0; ic < 3; ic++) {
#pragma unroll
            for (int ky = 0; ky < 3; ky++) {
                const float4* rp = (const float4*)(xb + ic * 380 + (oy + ky) * 20);
                float rr[20];
#pragma unroll
                for (int q = 0; q < 5; q++) {
                    float4 rv = rp[q];
                    rr[q * 4 + 0] = rv.x; rr[q * 4 + 1] = rv.y;
                    rr[q * 4 + 2] = rv.z; rr[q * 4 + 3] = rv.w;
                }
                int wbase = (ic * 3 + ky) * 3;
#pragma unroll
                for (int kx = 0; kx < 3; kx++) {
                    float4 wq = ((const float4*)w1t)[(wbase + kx) * 2 + ocg];
                    float wv[4] = {wq.x, wq.y, wq.z, wq.w};
#pragma unroll
                    for (int ox = 0; ox < 17; ox++) {
                        float r = rr[ox + kx];
                        acc[0][ox] += r * wv[0];
                        acc[1][ox] += r * wv[1];
                        acc[2][ox] += r * wv[2];
                        acc[3][ox] += r * wv[3];
                    }
                }
            }
        }
        int ocb = ocg * 4;
#pragma unroll
        for (int o = 0; o < 4; o++) {
            float ro[20];
#pragma unroll
            for (int ox = 0; ox < 17; ox++) ro[ox] = fmaxf(acc[o][ox], 0.f);
            ro[17] = 0.f; ro[18] = 0.f; ro[19] = 0.f;
            float4* op = (float4*)(c1s + nd * 2720 + (ocb + o) * 340 + oy * 20);
#pragma unroll
            for (int q = 0; q < 5; q++)
                op[q] = make_float4(ro[q * 4], ro[q * 4 + 1], ro[q * 4 + 2], ro[q * 4 + 3]);
        }
    }
    __syncthreads();

    // ---- conv2: 4 lanes per (node, oy); lane owns 2 input channels ----
    {
        int icg = t & 3;
        int pid = t >> 2;               // 0..63; need nLocal*7 (<=42)
        int nd  = pid / 7;
        int oy  = pid - nd * 7;
        bool valid = (nd < nLocal);
        int ndc = valid ? nd : 0;
        const float* ib = c1s + ndc * 2720;

        float acc[35];
#pragma unroll
        for (int j = 0; j < 35; j++) acc[j] = 0.f;

#pragma unroll
        for (int ii = 0; ii < 2; ii++) {
            int ic = icg * 2 + ii;
#pragma unroll
            for (int ky = 0; ky < 5; ky++) {
                const float4* rp = (const float4*)(ib + ic * 340 + (oy * 2 + ky) * 20);
                float rr[20];
#pragma unroll
                for (int q = 0; q < 5; q++) {
                    float4 rv = rp[q];
                    rr[q * 4 + 0] = rv.x; rr[q * 4 + 1] = rv.y;
                    rr[q * 4 + 2] = rv.z; rr[q * 4 + 3] = rv.w;
                }
                int wbase = (ic * 5 + ky) * 5;
#pragma unroll
                for (int kx = 0; kx < 5; kx++) {
                    float4 wqa = ((const float4*)w2t)[(wbase + kx) * 2 + 0];
                    float4 wqb = ((const float4*)w2t)[(wbase + kx) * 2 + 1];
                    float wv[5] = {wqa.x, wqa.y, wqa.z, wqa.w, wqb.x};
#pragma unroll
                    for (int ox = 0; ox < 7; ox++) {
                        float r = rr[ox * 2 + kx];
#pragma unroll
                        for (int oc = 0; oc < 5; oc++)
                            acc[oc * 7 + ox] += r * wv[oc];
                    }
                }
            }
        }
#pragma unroll
        for (int j = 0; j < 35; j++) {
            acc[j] += __shfl_xor_sync(0xffffffff, acc[j], 1);
            acc[j] += __shfl_xor_sync(0xffffffff, acc[j], 2);
        }
        if (valid && icg == 0) {
            float* fp = g_feat + (size_t)(node0 + nd) * 245 + oy * 7;
#pragma unroll
            for (int oc = 0; oc < 5; oc++) {
                float bias = w2t[1600 + oc];
#pragma unroll
                for (int ox = 0; ox < 7; ox++)
                    fp[oc * 49 + ox] = fmaxf(acc[oc * 7 + ox] + bias, 0.f);
            }
        }
    }
}

// ---------------- degree (weighted float + integer in-degree) ----------------
__global__ void k_deg(const int* __restrict__ ei, const float* __restrict__ ea, int E) {
    int e = blockIdx.x * blockDim.x + threadIdx.x;
    if (e >= E) return;
    int c = ei[E + e];
    atomicAdd(&g_deg[c], ea[e]);
    atomicAdd(&g_indeg[c], 1);
}

__global__ void k_dinv(int n) {
    int i = blockIdx.x * blockDim.x + threadIdx.x;
    if (i >= n) return;
    float d = g_deg[i];
    g_dinv[i] = (d > 0.f) ? rsqrtf(d) : 0.f;
}

// ---------------- single-block exclusive prefix scan of in-degrees ----------------
__global__ __launch_bounds__(1024) void k_scan(int n) {
    __shared__ int buf[2][1024];
    __shared__ int s_carry;
    int t = threadIdx.x;
    if (t == 0) s_carry = 0;
    __syncthreads();
    for (int base = 0; base < n; base += 1024) {
        int v = (base + t < n) ? g_indeg[base + t] : 0;
        buf[0][t] = v;
        __syncthreads();
        int src = 0;
#pragma unroll
        for (int d = 1; d < 1024; d <<= 1) {
            int val = buf[src][t];
            if (t >= d) val += buf[src][t - d];
            buf[1 - src][t] = val;
            src = 1 - src;
            __syncthreads();
        }
        int inc = buf[src][t];
        int carry = s_carry;
        if (base + t < n) {
            int excl = carry + inc - v;
            g_off[base + t] = excl;
            g_cur[base + t] = excl;
        }
        __syncthreads();
        if (t == 1023) s_carry = carry + inc;
        __syncthreads();
    }
    if (t == 0) g_off[n] = s_carry;
}

// ---------------- CSR build ----------------
__global__ void k_csr(const int* __restrict__ ei, const float* __restrict__ ea, int E) {
    int e = blockIdx.x * blockDim.x + threadIdx.x;
    if (e >= E) return;
    int r = ei[e];
    int c = ei[E + e];
    float nrm = 0.2f * g_dinv[r] * ea[e] * g_dinv[c];
    int pos = atomicAdd(&g_cur[c], 1);
    g_edge[pos] = make_int2(r, __float_as_int(nrm));
}

// ---------------- l1: feat[n,245] @ l1w.T + b, relu -> h0 (v4 inner loop) --------
__global__ __launch_bounds__(256) void k_l1(const float* __restrict__ l1w,
                                            const float* __restrict__ l1b, int n)
{
    __shared__ float As[16 * 132];
    __shared__ float Bs[16 * 132];
    int t = threadIdx.x;
    int tx = t & 15, ty = t >> 4;
    float acc[8][8];
#pragma unroll
    for (int i = 0; i < 8; i++)
#pragma unroll
        for (int j = 0; j < 8; j++) acc[i][j] = 0.f;

    int rowBase = blockIdx.x * 128;
    for (int k0 = 0; k0 < 245; k0 += 16) {
#pragma unroll
        for (int i = 0; i < 8; i++) {
            int e = t + i * 256;
            int m = e >> 4, kk = e & 15;
            int node = rowBase + m, k = k0 + kk;
            As[kk * 132 + m] = (node < n && k < 245) ? g_feat[(size_t)node * 245 + k] : 0.f;
            Bs[kk * 132 + m] = (k < 245) ? l1w[m * 245 + k] : 0.f;
        }
        __syncthreads();
#pragma unroll
        for (int kk = 0; kk < 16; kk++) {
            const float4* ap = (const float4*)(As + kk * 132 + ty * 8);
            const float4* bp = (const float4*)(Bs + kk * 132 + tx * 8);
            float4 a0 = ap[0], a1 = ap[1];
            float4 b0 = bp[0], b1 = bp[1];
            float a[8] = {a0.x, a0.y, a0.z, a0.w, a1.x, a1.y, a1.z, a1.w};
            float b[8] = {b0.x, b0.y, b0.z, b0.w, b1.x, b1.y, b1.z, b1.w};
#pragma unroll
            for (int i = 0; i < 8; i++)
#pragma unroll
                for (int j = 0; j < 8; j++) acc[i][j] += a[i] * b[j];
        }
        __syncthreads();
    }
    float4 lb0 = ((const float4*)l1b)[tx * 2];
    float4 lb1 = ((const float4*)l1b)[tx * 2 + 1];
    float lb[8] = {lb0.x, lb0.y, lb0.z, lb0.w, lb1.x, lb1.y, lb1.z, lb1.w};
#pragma unroll
    for (int i = 0; i < 8; i++) {
        int node = rowBase + ty * 8 + i;
        if (node >= n) continue;
        float o[8];
#pragma unroll
        for (int j = 0; j < 8; j++) o[j] = fmaxf(acc[i][j] + lb[j], 0.f);
        float4* op = (float4*)(g_h0 + (size_t)node * 128 + tx * 8);
        op[0] = make_float4(o[0], o[1], o[2], o[3]);
        op[1] = make_float4(o[4], o[5], o[6], o[7]);
    }
}

// ---------------- APPNP hop (gather, no atomics): one warp per dest node -------
__global__ __launch_bounds__(256) void k_hop(int which, int n) {
    int wid = (blockIdx.x * 256 + threadIdx.x) >> 5;
    int lane = threadIdx.x & 31;
    if (wid >= n) return;
    const float4* hin = (const float4*)(which ? g_h1 : g_h0);
    float4* hout = (float4*)(which ? g_h2 : g_h1);
    int off0 = g_off[wid], off1 = g_off[wid + 1];

    float4 acc = make_float4(0.f, 0.f, 0.f, 0.f);
    int e = off0;
    for (; e + 2 <= off1; e += 2) {
        int2 ra = g_edge[e];
        int2 rb = g_edge[e + 1];
        float4 v0 = hin[(size_t)ra.x * 32 + lane];
        float4 v1 = hin[(size_t)rb.x * 32 + lane];
        float w0 = __int_as_float(ra.y);
        float w1 = __int_as_float(rb.y);
        acc.x += w0 * v0.x; acc.y += w0 * v0.y; acc.z += w0 * v0.z; acc.w += w0 * v0.w;
        acc.x += w1 * v1.x; acc.y += w1 * v1.y; acc.z += w1 * v1.z; acc.w += w1 * v1.w;
    }
    if (e < off1) {
        int2 ra = g_edge[e];
        float4 v0 = hin[(size_t)ra.x * 32 + lane];
        float w0 = __int_as_float(ra.y);
        acc.x += w0 * v0.x; acc.y += w0 * v0.y; acc.z += w0 * v0.z; acc.w += w0 * v0.w;
    }
    float4 h0v = ((const float4*)g_h0)[(size_t)wid * 32 + lane];
    float4 o;
    o.x = acc.x + 0.8f * h0v.x;
    o.y = acc.y + 0.8f * h0v.y;
    o.z = acc.z + 0.8f * h0v.z;
    o.w = acc.w + 0.8f * h0v.w;
    hout[(size_t)wid * 32 + lane] = o;
}

// ---------------- BN stats over h2 ----------------
__global__ __launch_bounds__(256) void k_bnstats(int n) {
    int c = threadIdx.x & 127;
    int sub = threadIdx.x >> 7;
    int n0 = blockIdx.x * 128;
    float s = 0.f, sq = 0.f;
    for (int k = sub; k < 128; k += 2) {
        int node = n0 + k;
        if (node < n) {
            float v = g_h2[(size_t)node * 128 + c];
            s += v; sq += v * v;
        }
    }
    __shared__ float ss[256], sqq[256];
    ss[threadIdx.x] = s; sqq[threadIdx.x] = sq;
    __syncthreads();
    if (threadIdx.x < 128) {
        atomicAdd(&g_bnsum[c], ss[threadIdx.x] + ss[threadIdx.x + 128]);
        atomicAdd(&g_bnsq[c], sqq[threadIdx.x] + sqq[threadIdx.x + 128]);
    }
}

__global__ void k_bnfin(const float* __restrict__ gamma, const float* __restrict__ beta,
                        float invN) {
    int c = threadIdx.x;
    float mean = g_bnsum[c] * invN;
    float var = g_bnsq[c] * invN - mean * mean;
    float inv = rsqrtf(var + 1e-5f);
    float a = gamma[c] * inv;
    g_ab[c] = a;
    g_ab[128 + c] = beta[c] - mean * a;
}

// ---------------- normalize + write node_x + pool scatter ----------------
__global__ void k_pool(const int* __restrict__ batch, float* __restrict__ out, int n) {
    int idx = blockIdx.x * blockDim.x + threadIdx.x;
    if (idx >= n * 32) return;
    int node = idx >> 5, q = idx & 31;
    int c = q * 4;
    float4 v = ((const float4*)g_h2)[idx];
    float4 r;
    r.x = v.x * g_ab[c + 0] + g_ab[128 + c + 0];
    r.y = v.y * g_ab[c + 1] + g_ab[128 + c + 1];
    r.z = v.z * g_ab[c + 2] + g_ab[128 + c + 2];
    r.w = v.w * g_ab[c + 3] + g_ab[128 + c + 3];
    ((float4*)out)[640 + idx] = r;
    int g = batch[node];
    float* gp = g_gsum + (size_t)g * 128 + c;
    atomicAdd(gp + 0, r.x);
    atomicAdd(gp + 1, r.y);
    atomicAdd(gp + 2, r.z);
    atomicAdd(gp + 3, r.w);
}

__global__ void k_gcnt(const int* __restrict__ batch, int n) {
    int i = blockIdx.x * blockDim.x + threadIdx.x;
    if (i >= n) return;
    atomicAdd(&g_gcnt[batch[i]], 1.0f);
}

// ---------------- graph MLP classifier ----------------
__global__ __launch_bounds__(64) void k_mlp(const float* __restrict__ l2w,
                                            const float* __restrict__ l2b,
                                            const float* __restrict__ l3w,
                                            const float* __restrict__ l3b,
                                            float* __restrict__ out) {
    int g = blockIdx.x, t = threadIdx.x;
    __shared__ float gx[128], hid[64];
    float cnt = fmaxf(g_gcnt[g], 1.f);
    float ic = 1.f / cnt;
    gx[t]      = g_gsum[(size_t)g * 128 + t] * ic;
    gx[t + 64] = g_gsum[(size_t)g * 128 + 64 + t] * ic;
    __syncthreads();
    float s = l2b[t];
    const float* wr = l2w + t * 128;
#pragma unroll 8
    for (int c = 0; c < 128; c++) s += gx[c] * wr[c];
    hid[t] = fmaxf(s, 0.f);
    __syncthreads();
    if (t < 5) {
        float s2 = l3b[t];
        const float* wr3 = l3w + t * 64;
#pragma unroll 8
        for (int j = 0; j < 64; j++) s2 += hid[j] * wr3[j];
        out[g * 5 + t] = s2;
    }
}

// ---------------- launcher ----------------
extern "C" void kernel_launch(void* const* d_in, const int* in_sizes, int n_in,
                              void* d_out, int out_size) {
    int wb = (n_in > 4 && in_sizes[4] == 216) ? 4 : 5;

    const float* x     = (const float*)d_in[0];
    const int*   ei    = (const int*)d_in[1];
    const float* ea    = (const float*)d_in[2];
    const int*   batch = (const int*)d_in[3];
    const float* c1w = (const float*)d_in[wb + 0];
    const float* c1b = (const float*)d_in[wb + 1];
    const float* c2w = (const float*)d_in[wb + 2];
    const float* c2b = (const float*)d_in[wb + 3];
    const float* l1w = (const float*)d_in[wb + 4];
    const float* l1b = (const float*)d_in[wb + 5];
    const float* gam = (const float*)d_in[wb + 6];
    const float* bet = (const float*)d_in[wb + 7];
    const float* l2w = (const float*)d_in[wb + 8];
    const float* l2b = (const float*)d_in[wb + 9];
    const float* l3w = (const float*)d_in[wb + 10];
    const float* l3b = (const float*)d_in[wb + 11];

    int n = in_sizes[0] / 1083;
    int E = in_sizes[1] / 2;
    int G = (out_size - n * 128) / 5;
    float* out = (float*)d_out;

    int cnnSmem = CNN_SMEM_FLOATS * 4;
    cudaFuncSetAttribute(k_cnn, cudaFuncAttributeMaxDynamicSharedMemorySize, cnnSmem);

    k_zero<<<(GMAXG * 128 + 255) / 256, 256>>>(n);
    k_deg<<<(E + 255) / 256, 256>>>(ei, ea, E);
    k_dinv<<<(n + 255) / 256, 256>>>(n);
    k_cnn<<<(n + CNN_NPB - 1) / CNN_NPB, 256, cnnSmem>>>(x, c1w, c1b, c2w, c2b, n);
    k_scan<<<1, 1024>>>(n);
    k_csr<<<(E + 255) / 256, 256>>>(ei, ea, E);
    k_l1<<<(n + 127) / 128, 256>>>(l1w, l1b, n);

    int hopBlocks = (n * 32 + 255) / 256;
    k_hop<<<hopBlocks, 256>>>(0, n);
    k_hop<<<hopBlocks, 256>>>(1, n);

    k_bnstats<<<(n + 127) / 128, 256>>>(n);
    k_bnfin<<<1, 128>>>(gam, bet, 1.0f / (float)n);
    k_pool<<<(n * 32 + 255) / 256, 256>>>(batch, out, n);
    k_gcnt<<<(n + 255) / 256, 256>>>(batch, n);
    k_mlp<<<G, 64>>>(l2w, l2b, l3w, l3b, out);
}

// round 7
// speedup vs baseline: 1.0188x; 1.0188x over previous
#include <cuda_runtime.h>
#include <cuda_bf16.h>

typedef unsigned long long u64;

__device__ __forceinline__ u64 pack2(float lo, float hi) {
    u64 r; asm("mov.b64 %0,{%1,%2};" : "=l"(r) : "f"(lo), "f"(hi)); return r;
}
__device__ __forceinline__ void unpack2(u64 v, float& lo, float& hi) {
    asm("mov.b64 {%0,%1},%2;" : "=f"(lo), "=f"(hi) : "l"(v));
}
__device__ __forceinline__ u64 fma2(u64 a, u64 b, u64 c) {
    u64 d; asm("fma.rn.f32x2 %0,%1,%2,%3;" : "=l"(d) : "l"(a), "l"(b), "l"(c)); return d;
}

// ---------------- static scratch (no runtime allocation allowed) ----------------
#define NMAX 50048
#define EMAX 1664000
#define GMAXG 512

__device__ float g_feat[(size_t)NMAX * 245];
__device__ float g_h0[(size_t)NMAX * 128];
__device__ float g_h1[(size_t)NMAX * 128];
__device__ float g_h2[(size_t)NMAX * 128];
__device__ float g_deg[NMAX];
__device__ float g_dinv[NMAX];
__device__ int   g_indeg[NMAX];
__device__ int   g_off[NMAX + 1];
__device__ int   g_cur[NMAX];
__device__ int2  g_edge[EMAX];
__device__ float g_bnsum[128];
__device__ float g_bnsq[128];
__device__ float g_ab[256];
__device__ float g_gsum[GMAXG * 128];
__device__ float g_gcnt[GMAXG];

// ---------------- zero init ----------------
__global__ void k_zero(int n) {
    int i = blockIdx.x * blockDim.x + threadIdx.x;
    if (i < n) { g_deg[i] = 0.f; g_indeg[i] = 0; }
    if (i < 128) { g_bnsum[i] = 0.f; g_bnsq[i] = 0.f; }
    if (i < GMAXG * 128) g_gsum[i] = 0.f;
    if (i < GMAXG) g_gcnt[i] = 0.f;
}

// ---------------- CNN encoder: packed f32x2 FMA, 7 nodes / block ----------------
// odd row strides (19 / 17) -> conflict-free scalar LDS.
// smem floats: w1p[432] | w2p[1200] | w1s[216] | w1b[8] | w2b[8] | xs[7*1083] | c1s[7*2312] | pad16
#define CNN_NPB 7
#define SM_W1P  0
#define SM_W2P  432
#define SM_W1S  1632
#define SM_W1B  1848
#define SM_W2B  1856
#define SM_XS   1864
#define SM_C1S  (SM_XS + CNN_NPB * 1083)
#define CNN_SMEM_FLOATS (SM_C1S + CNN_NPB * 2312 + 16)

__global__ __launch_bounds__(256, 2) void k_cnn(
    const float* __restrict__ x,
    const float* __restrict__ c1w, const float* __restrict__ c1b,
    const float* __restrict__ c2w, const float* __restrict__ c2b, int n)
{
    extern __shared__ float sm[];
    float* w1p = sm + SM_W1P;   // [27 r][8 oc] float2 {w,w}
    float* w2p = sm + SM_W2P;   // [(ic*5+ky)*5+oc][3] float2: {w0,w1},{w2,w3},{w4,0}
    float* w1s = sm + SM_W1S;   // scalar copy of c1w (tail taps)
    float* w1b = sm + SM_W1B;
    float* w2b = sm + SM_W2B;
    float* xs  = sm + SM_XS;    // per node: [3][19][19]
    float* c1s = sm + SM_C1S;   // per node: [8][17][17]

    int t = threadIdx.x;
    int node0 = blockIdx.x * CNN_NPB;
    int nLocal = n - node0; if (nLocal > CNN_NPB) nLocal = CNN_NPB;
    if (nLocal <= 0) return;

    // conv1 weights: packed duplicated + scalar copy
    for (int i = t; i < 216; i += 256) {
        int oc = i / 27, r = i - oc * 27;
        float w = c1w[i];
        w1s[i] = w;
        w1p[(r * 8 + oc) * 2 + 0] = w;
        w1p[(r * 8 + oc) * 2 + 1] = w;
    }
    if (t < 8) w1b[t] = c1b[t];
    // conv2 packed weight pairs
    for (int i = t; i < 600; i += 256) {
        int j = i % 3, rest = i / 3;
        int oc = rest % 5, icky = rest / 5;           // icky = ic*5+ky
        const float* wp = c2w + oc * 200 + icky * 5;  // 5 taps
        float lo, hi;
        if (j == 0)      { lo = wp[0]; hi = wp[1]; }
        else if (j == 1) { lo = wp[2]; hi = wp[3]; }
        else             { lo = wp[4]; hi = 0.f;   }
        w2p[i * 2 + 0] = lo;
        w2p[i * 2 + 1] = hi;
    }
    if (t < 5) w2b[t] = c2b[t];

    int totx = nLocal * 1083;
    const float* xp = x + (size_t)node0 * 1083;
    for (int i = t; i < totx; i += 256) xs[i] = xp[i];
    __syncthreads();

    // ---- conv1: task = (node, oy, ocg of 4); packed over ox pairs ----
    int tasks1 = nLocal * 34;
    for (int tt = t; tt < tasks1; tt += 256) {
        int nd  = tt / 34;
        int rid = tt - nd * 34;
        int ocg = rid / 17;
        int oy  = rid - ocg * 17;
        int ocb = ocg * 4;
        const float* xb = xs + nd * 1083;

        u64 accp[4][8];
        float accs[4];
#pragma unroll
        for (int o = 0; o < 4; o++) {
            float b = w1b[ocb + o];
            u64 bb = pack2(b, b);
#pragma unroll
            for (int p = 0; p < 8; p++) accp[o][p] = bb;
            accs[o] = b;
        }
#pragma unroll
        for (int ic = 0; ic < 3; ic++) {
#pragma unroll
            for (int ky = 0; ky < 3; ky++) {
                const float* rowp = xb + ic * 361 + (oy + ky) * 19;
                float rr[19];
#pragma unroll
                for (int j = 0; j < 19; j++) rr[j] = rowp[j];
                u64 pe[9], po[8];
#pragma unroll
                for (int p = 0; p < 9; p++) pe[p] = pack2(rr[2 * p], rr[2 * p + 1]);
#pragma unroll
                for (int p = 0; p < 8; p++) po[p] = pack2(rr[2 * p + 1], rr[2 * p + 2]);
                int rbase = (ic * 3 + ky) * 3;
#pragma unroll
                for (int o = 0; o < 4; o++) {
                    int oc = ocb + o;
                    u64 w0 = *(const u64*)(w1p + ((rbase + 0) * 8 + oc) * 2);
                    u64 w1 = *(const u64*)(w1p + ((rbase + 1) * 8 + oc) * 2);
                    u64 w2 = *(const u64*)(w1p + ((rbase + 2) * 8 + oc) * 2);
#pragma unroll
                    for (int p = 0; p < 8; p++) {
                        u64 a = accp[o][p];
                        a = fma2(pe[p],     w0, a);
                        a = fma2(po[p],     w1, a);
                        a = fma2(pe[p + 1], w2, a);
                        accp[o][p] = a;
                    }
                    const float* wsc = w1s + oc * 27 + rbase;
                    accs[o] += rr[16] * wsc[0] + rr[17] * wsc[1] + rr[18] * wsc[2];
                }
            }
        }
#pragma unroll
        for (int o = 0; o < 4; o++) {
            float* op = c1s + nd * 2312 + (ocb + o) * 289 + oy * 17;
#pragma unroll
            for (int p = 0; p < 8; p++) {
                float lo, hi; unpack2(accp[o][p], lo, hi);
                op[2 * p]     = fmaxf(lo, 0.f);
                op[2 * p + 1] = fmaxf(hi, 0.f);
            }
            op[16] = fmaxf(accs[o], 0.f);
        }
    }
    __syncthreads();

    // ---- conv2: 4 lanes per (node, oy); lane owns 2 ics; kx-split packed acc ----
    {
        int icg = t & 3;
        int pid = t >> 2;               // 0..63; need nLocal*7 (<=49)
        int nd  = pid / 7;
        int oy  = pid - nd * 7;
        bool valid = (nd < nLocal);
        int ndc = valid ? nd : 0;
        const float* ib = c1s + ndc * 2312;

        u64 accp[35];
#pragma unroll
        for (int j = 0; j < 35; j++) accp[j] = 0ULL;

#pragma unroll
        for (int ii = 0; ii < 2; ii++) {
            int ic = icg * 2 + ii;
#pragma unroll
            for (int ky = 0; ky < 5; ky++) {
                const float* rowp = ib + ic * 289 + (oy * 2 + ky) * 17;
                float rr[18];
#pragma unroll
                for (int j = 0; j < 18; j++) rr[j] = rowp[j];   // rr[17] overread, x0 weight
                u64 pe[9];
#pragma unroll
                for (int p = 0; p < 9; p++) pe[p] = pack2(rr[2 * p], rr[2 * p + 1]);
                int base3 = ((ic * 5 + ky) * 5) * 3;
#pragma unroll
                for (int oc = 0; oc < 5; oc++) {
                    const u64* wp = (const u64*)(w2p + (base3 + oc * 3) * 2);
                    u64 wA = wp[0], wB = wp[1], wC = wp[2];
#pragma unroll
                    for (int ox = 0; ox < 7; ox++) {
                        u64 a = accp[oc * 7 + ox];
                        a = fma2(pe[ox],     wA, a);
                        a = fma2(pe[ox + 1], wB, a);
                        a = fma2(pe[ox + 2], wC, a);
                        accp[oc * 7 + ox] = a;
                    }
                }
            }
        }
        float accf[35];
#pragma unroll
        for (int j = 0; j < 35; j++) {
            float lo, hi; unpack2(accp[j], lo, hi);
            accf[j] = lo + hi;
        }
#pragma unroll
        for (int j = 0; j < 35; j++) {
            accf[j] += __shfl_xor_sync(0xffffffff, accf[j], 1);
            accf[j] += __shfl_xor_sync(0xffffffff, accf[j], 2);
        }
        if (valid && icg == 0) {
            float* fp = g_feat + (size_t)(node0 + nd) * 245 + oy * 7;
#pragma unroll
            for (int oc = 0; oc < 5; oc++) {
                float bias = w2b[oc];
#pragma unroll
                for (int ox = 0; ox < 7; ox++)
                    fp[oc * 49 + ox] = fmaxf(accf[oc * 7 + ox] + bias, 0.f);
            }
        }
    }
}

// ---------------- degree (weighted float + integer in-degree) ----------------
__global__ void k_deg(const int* __restrict__ ei, const float* __restrict__ ea, int E) {
    int e = blockIdx.x * blockDim.x + threadIdx.x;
    if (e >= E) return;
    int c = ei[E + e];
    atomicAdd(&g_deg[c], ea[e]);
    atomicAdd(&g_indeg[c], 1);
}

// ---------------- warp-shuffle scan of in-degrees (+ dinv folded in) -----------
__global__ __launch_bounds__(1024) void k_scan(int n) {
    __shared__ int ws[32];
    __shared__ int s_carry;
    int t = threadIdx.x;
    int lane = t & 31, wid = t >> 5;
    if (t == 0) s_carry = 0;
    __syncthreads();
    for (int base = 0; base < n; base += 1024) {
        int i = base + t;
        int v = (i < n) ? g_indeg[i] : 0;
        if (i < n) {
            float d = g_deg[i];
            g_dinv[i] = (d > 0.f) ? rsqrtf(d) : 0.f;
        }
        int inc = v;
#pragma unroll
        for (int d = 1; d < 32; d <<= 1) {
            int u = __shfl_up_sync(0xffffffffu, inc, d);
            if (lane >= d) inc += u;
        }
        if (lane == 31) ws[wid] = inc;
        __syncthreads();
        if (wid == 0) {
            int s = ws[lane];
#pragma unroll
            for (int d = 1; d < 32; d <<= 1) {
                int u = __shfl_up_sync(0xffffffffu, s, d);
                if (lane >= d) s += u;
            }
            ws[lane] = s;
        }
        __syncthreads();
        int chunkoff = wid ? ws[wid - 1] : 0;
        int carry = s_carry;
        int excl = carry + chunkoff + inc - v;
        if (i < n) { g_off[i] = excl; g_cur[i] = excl; }
        __syncthreads();
        if (t == 0) s_carry = carry + ws[31];
        __syncthreads();
    }
    if (t == 0) g_off[n] = s_carry;
}

// ---------------- CSR build ----------------
__global__ void k_csr(const int* __restrict__ ei, const float* __restrict__ ea, int E) {
    int e = blockIdx.x * blockDim.x + threadIdx.x;
    if (e >= E) return;
    int r = ei[e];
    int c = ei[E + e];
    float nrm = 0.2f * g_dinv[r] * ea[e] * g_dinv[c];
    int pos = atomicAdd(&g_cur[c], 1);
    g_edge[pos] = make_int2(r, __float_as_int(nrm));
}

// ---------------- l1: feat[n,245] @ l1w.T + b, relu -> h0 ----------------
__global__ __launch_bounds__(256) void k_l1(const float* __restrict__ l1w,
                                            const float* __restrict__ l1b, int n)
{
    __shared__ float As[16 * 132];
    __shared__ float Bs[16 * 132];
    int t = threadIdx.x;
    int tx = t & 15, ty = t >> 4;
    float acc[8][8];
#pragma unroll
    for (int i = 0; i < 8; i++)
#pragma unroll
        for (int j = 0; j < 8; j++) acc[i][j] = 0.f;

    int rowBase = blockIdx.x * 128;
    for (int k0 = 0; k0 < 245; k0 += 16) {
#pragma unroll
        for (int i = 0; i < 8; i++) {
            int e = t + i * 256;
            int m = e >> 4, kk = e & 15;
            int node = rowBase + m, k = k0 + kk;
            As[kk * 132 + m] = (node < n && k < 245) ? g_feat[(size_t)node * 245 + k] : 0.f;
            Bs[kk * 132 + m] = (k < 245) ? l1w[m * 245 + k] : 0.f;
        }
        __syncthreads();
#pragma unroll
        for (int kk = 0; kk < 16; kk++) {
            const float4* ap = (const float4*)(As + kk * 132 + ty * 8);
            const float4* bp = (const float4*)(Bs + kk * 132 + tx * 8);
            float4 a0 = ap[0], a1 = ap[1];
            float4 b0 = bp[0], b1 = bp[1];
            float a[8] = {a0.x, a0.y, a0.z, a0.w, a1.x, a1.y, a1.z, a1.w};
            float b[8] = {b0.x, b0.y, b0.z, b0.w, b1.x, b1.y, b1.z, b1.w};
#pragma unroll
            for (int i = 0; i < 8; i++)
#pragma unroll
                for (int j = 0; j < 8; j++) acc[i][j] += a[i] * b[j];
        }
        __syncthreads();
    }
    float4 lb0 = ((const float4*)l1b)[tx * 2];
    float4 lb1 = ((const float4*)l1b)[tx * 2 + 1];
    float lb[8] = {lb0.x, lb0.y, lb0.z, lb0.w, lb1.x, lb1.y, lb1.z, lb1.w};
#pragma unroll
    for (int i = 0; i < 8; i++) {
        int node = rowBase + ty * 8 + i;
        if (node >= n) continue;
        float o[8];
#pragma unroll
        for (int j = 0; j < 8; j++) o[j] = fmaxf(acc[i][j] + lb[j], 0.f);
        float4* op = (float4*)(g_h0 + (size_t)node * 128 + tx * 8);
        op[0] = make_float4(o[0], o[1], o[2], o[3]);
        op[1] = make_float4(o[4], o[5], o[6], o[7]);
    }
}

// ---------------- APPNP hop (gather, no atomics): one warp per dest node -------
__global__ __launch_bounds__(256) void k_hop(int which, int n) {
    int wid = (blockIdx.x * 256 + threadIdx.x) >> 5;
    int lane = threadIdx.x & 31;
    if (wid >= n) return;
    const float4* hin = (const float4*)(which ? g_h1 : g_h0);
    float4* hout = (float4*)(which ? g_h2 : g_h1);
    int off0 = g_off[wid], off1 = g_off[wid + 1];

    float4 acc = make_float4(0.f, 0.f, 0.f, 0.f);
    int e = off0;
    for (; e + 2 <= off1; e += 2) {
        int2 ra = g_edge[e];
        int2 rb = g_edge[e + 1];
        float4 v0 = hin[(size_t)ra.x * 32 + lane];
        float4 v1 = hin[(size_t)rb.x * 32 + lane];
        float w0 = __int_as_float(ra.y);
        float w1 = __int_as_float(rb.y);
        acc.x += w0 * v0.x; acc.y += w0 * v0.y; acc.z += w0 * v0.z; acc.w += w0 * v0.w;
        acc.x += w1 * v1.x; acc.y += w1 * v1.y; acc.z += w1 * v1.z; acc.w += w1 * v1.w;
    }
    if (e < off1) {
        int2 ra = g_edge[e];
        float4 v0 = hin[(size_t)ra.x * 32 + lane];
        float w0 = __int_as_float(ra.y);
        acc.x += w0 * v0.x; acc.y += w0 * v0.y; acc.z += w0 * v0.z; acc.w += w0 * v0.w;
    }
    float4 h0v = ((const float4*)g_h0)[(size_t)wid * 32 + lane];
    float4 o;
    o.x = acc.x + 0.8f * h0v.x;
    o.y = acc.y + 0.8f * h0v.y;
    o.z = acc.z + 0.8f * h0v.z;
    o.w = acc.w + 0.8f * h0v.w;
    hout[(size_t)wid * 32 + lane] = o;
}

// ---------------- BN stats over h2 ----------------
__global__ __launch_bounds__(256) void k_bnstats(int n) {
    int c = threadIdx.x & 127;
    int sub = threadIdx.x >> 7;
    int n0 = blockIdx.x * 128;
    float s = 0.f, sq = 0.f;
    for (int k = sub; k < 128; k += 2) {
        int node = n0 + k;
        if (node < n) {
            float v = g_h2[(size_t)node * 128 + c];
            s += v; sq += v * v;
        }
    }
    __shared__ float ss[256], sqq[256];
    ss[threadIdx.x] = s; sqq[threadIdx.x] = sq;
    __syncthreads();
    if (threadIdx.x < 128) {
        atomicAdd(&g_bnsum[c], ss[threadIdx.x] + ss[threadIdx.x + 128]);
        atomicAdd(&g_bnsq[c], sqq[threadIdx.x] + sqq[threadIdx.x + 128]);
    }
}

__global__ void k_bnfin(const float* __restrict__ gamma, const float* __restrict__ beta,
                        float invN) {
    int c = threadIdx.x;
    float mean = g_bnsum[c] * invN;
    float var = g_bnsq[c] * invN - mean * mean;
    float inv = rsqrtf(var + 1e-5f);
    float a = gamma[c] * inv;
    g_ab[c] = a;
    g_ab[128 + c] = beta[c] - mean * a;
}

// ---------------- normalize + write node_x + pool scatter ----------------
__global__ void k_pool(const int* __restrict__ batch, float* __restrict__ out, int n) {
    int idx = blockIdx.x * blockDim.x + threadIdx.x;
    if (idx >= n * 32) return;
    int node = idx >> 5, q = idx & 31;
    int c = q * 4;
    float4 v = ((const float4*)g_h2)[idx];
    float4 r;
    r.x = v.x * g_ab[c + 0] + g_ab[128 + c + 0];
    r.y = v.y * g_ab[c + 1] + g_ab[128 + c + 1];
    r.z = v.z * g_ab[c + 2] + g_ab[128 + c + 2];
    r.w = v.w * g_ab[c + 3] + g_ab[128 + c + 3];
    ((float4*)out)[640 + idx] = r;
    int g = batch[node];
    float* gp = g_gsum + (size_t)g * 128 + c;
    atomicAdd(gp + 0, r.x);
    atomicAdd(gp + 1, r.y);
    atomicAdd(gp + 2, r.z);
    atomicAdd(gp + 3, r.w);
}

__global__ void k_gcnt(const int* __restrict__ batch, int n) {
    int i = blockIdx.x * blockDim.x + threadIdx.x;
    if (i >= n) return;
    atomicAdd(&g_gcnt[batch[i]], 1.0f);
}

// ---------------- graph MLP classifier ----------------
__global__ __launch_bounds__(64) void k_mlp(const float* __restrict__ l2w,
                                            const float* __restrict__ l2b,
                                            const float* __restrict__ l3w,
                                            const float* __restrict__ l3b,
                                            float* __restrict__ out) {
    int g = blockIdx.x, t = threadIdx.x;
    __shared__ float gx[128], hid[64];
    float cnt = fmaxf(g_gcnt[g], 1.f);
    float ic = 1.f / cnt;
    gx[t]      = g_gsum[(size_t)g * 128 + t] * ic;
    gx[t + 64] = g_gsum[(size_t)g * 128 + 64 + t] * ic;
    __syncthreads();
    float s = l2b[t];
    const float* wr = l2w + t * 128;
#pragma unroll 8
    for (int c = 0; c < 128; c++) s += gx[c] * wr[c];
    hid[t] = fmaxf(s, 0.f);
    __syncthreads();
    if (t < 5) {
        float s2 = l3b[t];
        const float* wr3 = l3w + t * 64;
#pragma unroll 8
        for (int j = 0; j < 64; j++) s2 += hid[j] * wr3[j];
        out[g * 5 + t] = s2;
    }
}

// ---------------- launcher ----------------
extern "C" void kernel_launch(void* const* d_in, const int* in_sizes, int n_in,
                              void* d_out, int out_size) {
    int wb = (n_in > 4 && in_sizes[4] == 216) ? 4 : 5;

    const float* x     = (const float*)d_in[0];
    const int*   ei    = (const int*)d_in[1];
    const float* ea    = (const float*)d_in[2];
    const int*   batch = (const int*)d_in[3];
    const float* c1w = (const float*)d_in[wb + 0];
    const float* c1b = (const float*)d_in[wb + 1];
    const float* c2w = (const float*)d_in[wb + 2];
    const float* c2b = (const float*)d_in[wb + 3];
    const float* l1w = (const float*)d_in[wb + 4];
    const float* l1b = (const float*)d_in[wb + 5];
    const float* gam = (const float*)d_in[wb + 6];
    const float* bet = (const float*)d_in[wb + 7];
    const float* l2w = (const float*)d_in[wb + 8];
    const float* l2b = (const float*)d_in[wb + 9];
    const float* l3w = (const float*)d_in[wb + 10];
    const float* l3b = (const float*)d_in[wb + 11];

    int n = in_sizes[0] / 1083;
    int E = in_sizes[1] / 2;
    int G = (out_size - n * 128) / 5;
    float* out = (float*)d_out;

    int cnnSmem = CNN_SMEM_FLOATS * 4;
    cudaFuncSetAttribute(k_cnn, cudaFuncAttributeMaxDynamicSharedMemorySize, cnnSmem);

    k_zero<<<(GMAXG * 128 + 255) / 256, 256>>>(n);
    k_deg<<<(E + 255) / 256, 256>>>(ei, ea, E);
    k_scan<<<1, 1024>>>(n);
    k_cnn<<<(n + CNN_NPB - 1) / CNN_NPB, 256, cnnSmem>>>(x, c1w, c1b, c2w, c2b, n);
    k_csr<<<(E + 255) / 256, 256>>>(ei, ea, E);
    k_l1<<<(n + 127) / 128, 256>>>(l1w, l1b, n);

    int hopBlocks = (n * 32 + 255) / 256;
    k_hop<<<hopBlocks, 256>>>(0, n);
    k_hop<<<hopBlocks, 256>>>(1, n);

    k_bnstats<<<(n + 127) / 128, 256>>>(n);
    k_bnfin<<<1, 128>>>(gam, bet, 1.0f / (float)n);
    k_pool<<<(n * 32 + 255) / 256, 256>>>(batch, out, n);
    k_gcnt<<<(n + 255) / 256, 256>>>(batch, n);
    k_mlp<<<G, 64>>>(l2w, l2b, l3w, l3b, out);
}

// round 8
// speedup vs baseline: 1.1845x; 1.1626x over previous
#include <cuda_runtime.h>
#include <cuda_bf16.h>

// ---------------- static scratch (no runtime allocation allowed) ----------------
#define NMAX 50048
#define EMAX 1664000
#define GMAXG 512

__device__ float g_feat[(size_t)NMAX * 245];
__device__ float g_h0[(size_t)NMAX * 128];
__device__ float g_h1[(size_t)NMAX * 128];
__device__ float g_h2[(size_t)NMAX * 128];
__device__ float g_deg[NMAX];
__device__ float g_dinv[NMAX];
__device__ int   g_indeg[NMAX];
__device__ int   g_off[NMAX + 1];
__device__ int   g_cur[NMAX];
__device__ int2  g_edge[EMAX];
__device__ float g_bnsum[128];
__device__ float g_bnsq[128];
__device__ float g_ab[256];
__device__ float g_gsum[GMAXG * 128];
__device__ float g_gcnt[GMAXG];

// ---------------- zero init ----------------
__global__ void k_zero(int n) {
    int i = blockIdx.x * blockDim.x + threadIdx.x;
    if (i < n) { g_deg[i] = 0.f; g_indeg[i] = 0; }
    if (i < 128) { g_bnsum[i] = 0.f; g_bnsq[i] = 0.f; }
    if (i < GMAXG * 128) g_gsum[i] = 0.f;
    if (i < GMAXG) g_gcnt[i] = 0.f;
}

// ---------------- CNN encoder (R5 best version): oc-grouped register tiles -----
// odd strides (19/17) -> conflict-free scalar LDS. 7 nodes / block.
#define CNN_NPB 7
#define SM_W1   0
#define SM_W2   224
#define SM_XS   1232
#define SM_C1S  (1232 + CNN_NPB * 1083)
#define CNN_SMEM_FLOATS (SM_C1S + CNN_NPB * 2312)

__global__ __launch_bounds__(256, 2) void k_cnn(
    const float* __restrict__ x,
    const float* __restrict__ c1w, const float* __restrict__ c1b,
    const float* __restrict__ c2w, const float* __restrict__ c2b, int n)
{
    extern __shared__ float sm[];
    float* w1  = sm + SM_W1;
    float* w2  = sm + SM_W2;
    float* xs  = sm + SM_XS;
    float* c1s = sm + SM_C1S;

    int t = threadIdx.x;
    int node0 = blockIdx.x * CNN_NPB;
    int nLocal = n - node0; if (nLocal > CNN_NPB) nLocal = CNN_NPB;
    if (nLocal <= 0) return;

    for (int i = t; i < 216; i += 256) w1[i] = c1w[i];
    if (t < 8) w1[216 + t] = c1b[t];
    for (int i = t; i < 1000; i += 256) w2[i] = c2w[i];
    if (t < 5) w2[1000 + t] = c2b[t];

    int totx = nLocal * 1083;
    const float* xp = x + (size_t)node0 * 1083;
    for (int i = t; i < totx; i += 256) xs[i] = xp[i];
    __syncthreads();

    // ---- conv1: task = (node, oy, ocg of 4); thread computes 4x17 outputs ----
    int tasks1 = nLocal * 34;
    for (int tt = t; tt < tasks1; tt += 256) {
        int nd  = tt / 34;
        int rid = tt - nd * 34;
        int ocg = rid / 17;
        int oy  = rid - ocg * 17;
        int ocb = ocg * 4;
        const float* xb = xs + nd * 1083;

        float acc[4][17];
#pragma unroll
        for (int o = 0; o < 4; o++) {
            float bias = w1[216 + ocb + o];
#pragma unroll
            for (int ox = 0; ox < 17; ox++) acc[o][ox] = bias;
        }
#pragma unroll
        for (int ic = 0; ic < 3; ic++) {
#pragma unroll
            for (int ky = 0; ky < 3; ky++) {
                const float* rowp = xb + ic * 361 + (oy + ky) * 19;
                float rr[19];
#pragma unroll
                for (int j = 0; j < 19; j++) rr[j] = rowp[j];
#pragma unroll
                for (int o = 0; o < 4; o++) {
                    const float* wp = w1 + (ocb + o) * 27 + ic * 9 + ky * 3;
                    float wa = wp[0], wbv = wp[1], wc = wp[2];
#pragma unroll
                    for (int ox = 0; ox < 17; ox++)
                        acc[o][ox] += rr[ox] * wa + rr[ox + 1] * wbv + rr[ox + 2] * wc;
                }
            }
        }
#pragma unroll
        for (int o = 0; o < 4; o++) {
            float* op = c1s + nd * 2312 + (ocb + o) * 289 + oy * 17;
#pragma unroll
            for (int ox = 0; ox < 17; ox++) op[ox] = fmaxf(acc[o][ox], 0.f);
        }
    }
    __syncthreads();

    // ---- conv2: 4 lanes per (node, oy); each lane 2 ics; shuffle reduce ----
    {
        int icg = t & 3;
        int pid = t >> 2;
        int nd  = pid / 7;
        int oy  = pid - nd * 7;
        bool valid = (nd < nLocal);
        int ndc = valid ? nd : 0;
        const float* ib = c1s + ndc * 2312;

        float acc[35];
#pragma unroll
        for (int j = 0; j < 35; j++) acc[j] = 0.f;

#pragma unroll
        for (int ii = 0; ii < 2; ii++) {
            int ic = icg * 2 + ii;
#pragma unroll
            for (int ky = 0; ky < 5; ky++) {
                const float* rowp = ib + ic * 289 + (oy * 2 + ky) * 17;
                float rr[17];
#pragma unroll
                for (int j = 0; j < 17; j++) rr[j] = rowp[j];
#pragma unroll
                for (int oc = 0; oc < 5; oc++) {
                    const float* wp = w2 + oc * 200 + ic * 25 + ky * 5;
                    float wv[5];
#pragma unroll
                    for (int kx = 0; kx < 5; kx++) wv[kx] = wp[kx];
#pragma unroll
                    for (int ox = 0; ox < 7; ox++) {
#pragma unroll
                        for (int kx = 0; kx < 5; kx++)
                            acc[oc * 7 + ox] += rr[ox * 2 + kx] * wv[kx];
                    }
                }
            }
        }
#pragma unroll
        for (int j = 0; j < 35; j++) {
            acc[j] += __shfl_xor_sync(0xffffffff, acc[j], 1);
            acc[j] += __shfl_xor_sync(0xffffffff, acc[j], 2);
        }
        if (valid && icg == 0) {
            float* fp = g_feat + (size_t)(node0 + nd) * 245 + oy * 7;
#pragma unroll
            for (int oc = 0; oc < 5; oc++) {
                float bias = w2[1000 + oc];
#pragma unroll
                for (int ox = 0; ox < 7; ox++)
                    fp[oc * 49 + ox] = fmaxf(acc[oc * 7 + ox] + bias, 0.f);
            }
        }
    }
}

// ---------------- degree (weighted float + integer in-degree) ----------------
__global__ void k_deg(const int* __restrict__ ei, const float* __restrict__ ea, int E) {
    int e = blockIdx.x * blockDim.x + threadIdx.x;
    if (e >= E) return;
    int c = ei[E + e];
    atomicAdd(&g_deg[c], ea[e]);
    atomicAdd(&g_indeg[c], 1);
}

// ---------------- warp-shuffle scan of in-degrees (+ dinv folded in) -----------
__global__ __launch_bounds__(1024) void k_scan(int n) {
    __shared__ int ws[32];
    __shared__ int s_carry;
    int t = threadIdx.x;
    int lane = t & 31, wid = t >> 5;
    if (t == 0) s_carry = 0;
    __syncthreads();
    for (int base = 0; base < n; base += 1024) {
        int i = base + t;
        int v = (i < n) ? g_indeg[i] : 0;
        if (i < n) {
            float d = g_deg[i];
            g_dinv[i] = (d > 0.f) ? rsqrtf(d) : 0.f;
        }
        int inc = v;
#pragma unroll
        for (int d = 1; d < 32; d <<= 1) {
            int u = __shfl_up_sync(0xffffffffu, inc, d);
            if (lane >= d) inc += u;
        }
        if (lane == 31) ws[wid] = inc;
        __syncthreads();
        if (wid == 0) {
            int s = ws[lane];
#pragma unroll
            for (int d = 1; d < 32; d <<= 1) {
                int u = __shfl_up_sync(0xffffffffu, s, d);
                if (lane >= d) s += u;
            }
            ws[lane] = s;
        }
        __syncthreads();
        int chunkoff = wid ? ws[wid - 1] : 0;
        int carry = s_carry;
        int excl = carry + chunkoff + inc - v;
        if (i < n) { g_off[i] = excl; g_cur[i] = excl; }
        __syncthreads();
        if (t == 0) s_carry = carry + ws[31];
        __syncthreads();
    }
    if (t == 0) g_off[n] = s_carry;
}

// ---------------- CSR build ----------------
__global__ void k_csr(const int* __restrict__ ei, const float* __restrict__ ea, int E) {
    int e = blockIdx.x * blockDim.x + threadIdx.x;
    if (e >= E) return;
    int r = ei[e];
    int c = ei[E + e];
    float nrm = 0.2f * g_dinv[r] * ea[e] * g_dinv[c];
    int pos = atomicAdd(&g_cur[c], 1);
    g_edge[pos] = make_int2(r, __float_as_int(nrm));
}

// ---------------- l1: feat[n,245] @ l1w.T + b, relu -> h0 ----------------
__global__ __launch_bounds__(256) void k_l1(const float* __restrict__ l1w,
                                            const float* __restrict__ l1b, int n)
{
    __shared__ float As[16 * 132];
    __shared__ float Bs[16 * 132];
    int t = threadIdx.x;
    int tx = t & 15, ty = t >> 4;
    float acc[8][8];
#pragma unroll
    for (int i = 0; i < 8; i++)
#pragma unroll
        for (int j = 0; j < 8; j++) acc[i][j] = 0.f;

    int rowBase = blockIdx.x * 128;
    for (int k0 = 0; k0 < 245; k0 += 16) {
#pragma unroll
        for (int i = 0; i < 8; i++) {
            int e = t + i * 256;
            int m = e >> 4, kk = e & 15;
            int node = rowBase + m, k = k0 + kk;
            As[kk * 132 + m] = (node < n && k < 245) ? g_feat[(size_t)node * 245 + k] : 0.f;
            Bs[kk * 132 + m] = (k < 245) ? l1w[m * 245 + k] : 0.f;
        }
        __syncthreads();
#pragma unroll
        for (int kk = 0; kk < 16; kk++) {
            const float4* ap = (const float4*)(As + kk * 132 + ty * 8);
            const float4* bp = (const float4*)(Bs + kk * 132 + tx * 8);
            float4 a0 = ap[0], a1 = ap[1];
            float4 b0 = bp[0], b1 = bp[1];
            float a[8] = {a0.x, a0.y, a0.z, a0.w, a1.x, a1.y, a1.z, a1.w};
            float b[8] = {b0.x, b0.y, b0.z, b0.w, b1.x, b1.y, b1.z, b1.w};
#pragma unroll
            for (int i = 0; i < 8; i++)
#pragma unroll
                for (int j = 0; j < 8; j++) acc[i][j] += a[i] * b[j];
        }
        __syncthreads();
    }
    float4 lb0 = ((const float4*)l1b)[tx * 2];
    float4 lb1 = ((const float4*)l1b)[tx * 2 + 1];
    float lb[8] = {lb0.x, lb0.y, lb0.z, lb0.w, lb1.x, lb1.y, lb1.z, lb1.w};
#pragma unroll
    for (int i = 0; i < 8; i++) {
        int node = rowBase + ty * 8 + i;
        if (node >= n) continue;
        float o[8];
#pragma unroll
        for (int j = 0; j < 8; j++) o[j] = fmaxf(acc[i][j] + lb[j], 0.f);
        float4* op = (float4*)(g_h0 + (size_t)node * 128 + tx * 8);
        op[0] = make_float4(o[0], o[1], o[2], o[3]);
        op[1] = make_float4(o[4], o[5], o[6], o[7]);
    }
}

// ---------------- APPNP hop; hop2 (which=1) fuses BN statistics ----------------
__global__ __launch_bounds__(256) void k_hop(int which, int n) {
    __shared__ float ssum[128], ssq[128];
    int t = threadIdx.x;
    if (which) {
        if (t < 128) { ssum[t] = 0.f; ssq[t] = 0.f; }
        __syncthreads();
    }
    int wid = (blockIdx.x * 256 + t) >> 5;
    int lane = t & 31;
    bool valid = (wid < n);

    float4 o = make_float4(0.f, 0.f, 0.f, 0.f);
    if (valid) {
        const float4* hin = (const float4*)(which ? g_h1 : g_h0);
        float4* hout = (float4*)(which ? g_h2 : g_h1);
        int off0 = g_off[wid], off1 = g_off[wid + 1];

        float4 acc = make_float4(0.f, 0.f, 0.f, 0.f);
        int e = off0;
        for (; e + 2 <= off1; e += 2) {
            int2 ra = g_edge[e];
            int2 rb = g_edge[e + 1];
            float4 v0 = hin[(size_t)ra.x * 32 + lane];
            float4 v1 = hin[(size_t)rb.x * 32 + lane];
            float w0 = __int_as_float(ra.y);
            float w1 = __int_as_float(rb.y);
            acc.x += w0 * v0.x; acc.y += w0 * v0.y; acc.z += w0 * v0.z; acc.w += w0 * v0.w;
            acc.x += w1 * v1.x; acc.y += w1 * v1.y; acc.z += w1 * v1.z; acc.w += w1 * v1.w;
        }
        if (e < off1) {
            int2 ra = g_edge[e];
            float4 v0 = hin[(size_t)ra.x * 32 + lane];
            float w0 = __int_as_float(ra.y);
            acc.x += w0 * v0.x; acc.y += w0 * v0.y; acc.z += w0 * v0.z; acc.w += w0 * v0.w;
        }
        float4 h0v = ((const float4*)g_h0)[(size_t)wid * 32 + lane];
        o.x = acc.x + 0.8f * h0v.x;
        o.y = acc.y + 0.8f * h0v.y;
        o.z = acc.z + 0.8f * h0v.z;
        o.w = acc.w + 0.8f * h0v.w;
        hout[(size_t)wid * 32 + lane] = o;
    }
    if (which) {
        if (valid) {
            int c = lane * 4;
            atomicAdd(&ssum[c + 0], o.x); atomicAdd(&ssq[c + 0], o.x * o.x);
            atomicAdd(&ssum[c + 1], o.y); atomicAdd(&ssq[c + 1], o.y * o.y);
            atomicAdd(&ssum[c + 2], o.z); atomicAdd(&ssq[c + 2], o.z * o.z);
            atomicAdd(&ssum[c + 3], o.w); atomicAdd(&ssq[c + 3], o.w * o.w);
        }
        __syncthreads();
        if (t < 128) {
            atomicAdd(&g_bnsum[t], ssum[t]);
            atomicAdd(&g_bnsq[t], ssq[t]);
        }
    }
}

__global__ void k_bnfin(const float* __restrict__ gamma, const float* __restrict__ beta,
                        float invN) {
    int c = threadIdx.x;
    float mean = g_bnsum[c] * invN;
    float var = g_bnsq[c] * invN - mean * mean;
    float inv = rsqrtf(var + 1e-5f);
    float a = gamma[c] * inv;
    g_ab[c] = a;
    g_ab[128 + c] = beta[c] - mean * a;
}

// ---------------- normalize + write node_x + pool scatter ----------------
__global__ void k_pool(const int* __restrict__ batch, float* __restrict__ out, int n) {
    int idx = blockIdx.x * blockDim.x + threadIdx.x;
    if (idx >= n * 32) return;
    int node = idx >> 5, q = idx & 31;
    int c = q * 4;
    float4 v = ((const float4*)g_h2)[idx];
    float4 r;
    r.x = v.x * g_ab[c + 0] + g_ab[128 + c + 0];
    r.y = v.y * g_ab[c + 1] + g_ab[128 + c + 1];
    r.z = v.z * g_ab[c + 2] + g_ab[128 + c + 2];
    r.w = v.w * g_ab[c + 3] + g_ab[128 + c + 3];
    ((float4*)out)[640 + idx] = r;
    int g = batch[node];
    float* gp = g_gsum + (size_t)g * 128 + c;
    atomicAdd(gp + 0, r.x);
    atomicAdd(gp + 1, r.y);
    atomicAdd(gp + 2, r.z);
    atomicAdd(gp + 3, r.w);
}

__global__ void k_gcnt(const int* __restrict__ batch, int n) {
    int i = blockIdx.x * blockDim.x + threadIdx.x;
    if (i >= n) return;
    atomicAdd(&g_gcnt[batch[i]], 1.0f);
}

// ---------------- graph MLP classifier ----------------
__global__ __launch_bounds__(64) void k_mlp(const float* __restrict__ l2w,
                                            const float* __restrict__ l2b,
                                            const float* __restrict__ l3w,
                                            const float* __restrict__ l3b,
                                            float* __restrict__ out) {
    int g = blockIdx.x, t = threadIdx.x;
    __shared__ float gx[128], hid[64];
    float cnt = fmaxf(g_gcnt[g], 1.f);
    float ic = 1.f / cnt;
    gx[t]      = g_gsum[(size_t)g * 128 + t] * ic;
    gx[t + 64] = g_gsum[(size_t)g * 128 + 64 + t] * ic;
    __syncthreads();
    float s = l2b[t];
    const float* wr = l2w + t * 128;
#pragma unroll 8
    for (int c = 0; c < 128; c++) s += gx[c] * wr[c];
    hid[t] = fmaxf(s, 0.f);
    __syncthreads();
    if (t < 5) {
        float s2 = l3b[t];
        const float* wr3 = l3w + t * 64;
#pragma unroll 8
        for (int j = 0; j < 64; j++) s2 += hid[j] * wr3[j];
        out[g * 5 + t] = s2;
    }
}

// ---------------- launcher (two-stream fork/join, graph-capturable) -----------
extern "C" void kernel_launch(void* const* d_in, const int* in_sizes, int n_in,
                              void* d_out, int out_size) {
    static cudaStream_t sB = nullptr;
    static cudaEvent_t evFork = nullptr, evJoin = nullptr;
    if (sB == nullptr) {
        cudaStreamCreateWithFlags(&sB, cudaStreamNonBlocking);
        cudaEventCreateWithFlags(&evFork, cudaEventDisableTiming);
        cudaEventCreateWithFlags(&evJoin, cudaEventDisableTiming);
    }

    int wb = (n_in > 4 && in_sizes[4] == 216) ? 4 : 5;

    const float* x     = (const float*)d_in[0];
    const int*   ei    = (const int*)d_in[1];
    const float* ea    = (const float*)d_in[2];
    const int*   batch = (const int*)d_in[3];
    const float* c1w = (const float*)d_in[wb + 0];
    const float* c1b = (const float*)d_in[wb + 1];
    const float* c2w = (const float*)d_in[wb + 2];
    const float* c2b = (const float*)d_in[wb + 3];
    const float* l1w = (const float*)d_in[wb + 4];
    const float* l1b = (const float*)d_in[wb + 5];
    const float* gam = (const float*)d_in[wb + 6];
    const float* bet = (const float*)d_in[wb + 7];
    const float* l2w = (const float*)d_in[wb + 8];
    const float* l2b = (const float*)d_in[wb + 9];
    const float* l3w = (const float*)d_in[wb + 10];
    const float* l3b = (const float*)d_in[wb + 11];

    int n = in_sizes[0] / 1083;
    int E = in_sizes[1] / 2;
    int G = (out_size - n * 128) / 5;
    float* out = (float*)d_out;

    int cnnSmem = CNN_SMEM_FLOATS * 4;
    cudaFuncSetAttribute(k_cnn, cudaFuncAttributeMaxDynamicSharedMemorySize, cnnSmem);

    // stream 0: zero, then fork
    k_zero<<<(GMAXG * 128 + 255) / 256, 256>>>(n);
    cudaEventRecord(evFork, 0);
    cudaStreamWaitEvent(sB, evFork, 0);

    // stream B: edge preprocessing chain (independent of CNN path)
    k_deg<<<(E + 255) / 256, 256, 0, sB>>>(ei, ea, E);
    k_scan<<<1, 1024, 0, sB>>>(n);
    k_csr<<<(E + 255) / 256, 256, 0, sB>>>(ei, ea, E);
    k_gcnt<<<(n + 255) / 256, 256, 0, sB>>>(batch, n);
    cudaEventRecord(evJoin, sB);

    // stream 0: node encoder path (overlaps with stream B)
    k_cnn<<<(n + CNN_NPB - 1) / CNN_NPB, 256, cnnSmem>>>(x, c1w, c1b, c2w, c2b, n);
    k_l1<<<(n + 127) / 128, 256>>>(l1w, l1b, n);

    // join, then the dependent tail
    cudaStreamWaitEvent(0, evJoin, 0);
    int hopBlocks = (n * 32 + 255) / 256;
    k_hop<<<hopBlocks, 256>>>(0, n);
    k_hop<<<hopBlocks, 256>>>(1, n);   // fused BN stats

    k_bnfin<<<1, 128>>>(gam, bet, 1.0f / (float)n);
    k_pool<<<(n * 32 + 255) / 256, 256>>>(batch, out, n);
    k_mlp<<<G, 64>>>(l2w, l2b, l3w, l3b, out);
}

// round 9
// speedup vs baseline: 1.1995x; 1.0127x over previous
#include <cuda_runtime.h>
#include <cuda_bf16.h>
#include <cuda_fp16.h>

// ---------------- static scratch (no runtime allocation allowed) ----------------
#define NMAX 50048
#define EMAX 1664000
#define GMAXG 512

__device__ float   g_feat[(size_t)NMAX * 245];
__device__ float   g_h0[(size_t)NMAX * 128];
__device__ float   g_h1[(size_t)NMAX * 128];
__device__ float   g_h2[(size_t)NMAX * 128];
__device__ __half2 g_h0h[(size_t)NMAX * 64];   // fp16 mirror of h0 (gather source)
__device__ __half2 g_h1h[(size_t)NMAX * 64];   // fp16 mirror of h1 (gather source)
__device__ float   g_deg[NMAX];
__device__ float   g_dinv[NMAX];
__device__ int     g_indeg[NMAX];
__device__ int     g_off[NMAX + 1];
__device__ int     g_cur[NMAX];
__device__ int2    g_edge[EMAX];
__device__ float   g_bnsum[128];
__device__ float   g_bnsq[128];
__device__ float   g_ab[256];
__device__ float   g_gsum[GMAXG * 128];
__device__ float   g_gcnt[GMAXG];

// ---------------- zero init ----------------
__global__ void k_zero(int n) {
    int i = blockIdx.x * blockDim.x + threadIdx.x;
    if (i < n) { g_deg[i] = 0.f; g_indeg[i] = 0; }
    if (i < 128) { g_bnsum[i] = 0.f; g_bnsq[i] = 0.f; }
    if (i < GMAXG * 128) g_gsum[i] = 0.f;
    if (i < GMAXG) g_gcnt[i] = 0.f;
}

// ---------------- CNN encoder (best version): oc-grouped register tiles --------
#define CNN_NPB 7
#define SM_W1   0
#define SM_W2   224
#define SM_XS   1232
#define SM_C1S  (1232 + CNN_NPB * 1083)
#define CNN_SMEM_FLOATS (SM_C1S + CNN_NPB * 2312)

__global__ __launch_bounds__(256, 2) void k_cnn(
    const float* __restrict__ x,
    const float* __restrict__ c1w, const float* __restrict__ c1b,
    const float* __restrict__ c2w, const float* __restrict__ c2b, int n)
{
    extern __shared__ float sm[];
    float* w1  = sm + SM_W1;
    float* w2  = sm + SM_W2;
    float* xs  = sm + SM_XS;
    float* c1s = sm + SM_C1S;

    int t = threadIdx.x;
    int node0 = blockIdx.x * CNN_NPB;
    int nLocal = n - node0; if (nLocal > CNN_NPB) nLocal = CNN_NPB;
    if (nLocal <= 0) return;

    for (int i = t; i < 216; i += 256) w1[i] = c1w[i];
    if (t < 8) w1[216 + t] = c1b[t];
    for (int i = t; i < 1000; i += 256) w2[i] = c2w[i];
    if (t < 5) w2[1000 + t] = c2b[t];

    int totx = nLocal * 1083;
    const float* xp = x + (size_t)node0 * 1083;
    for (int i = t; i < totx; i += 256) xs[i] = xp[i];
    __syncthreads();

    int tasks1 = nLocal * 34;
    for (int tt = t; tt < tasks1; tt += 256) {
        int nd  = tt / 34;
        int rid = tt - nd * 34;
        int ocg = rid / 17;
        int oy  = rid - ocg * 17;
        int ocb = ocg * 4;
        const float* xb = xs + nd * 1083;

        float acc[4][17];
#pragma unroll
        for (int o = 0; o < 4; o++) {
            float bias = w1[216 + ocb + o];
#pragma unroll
            for (int ox = 0; ox < 17; ox++) acc[o][ox] = bias;
        }
#pragma unroll
        for (int ic = 0; ic < 3; ic++) {
#pragma unroll
            for (int ky = 0; ky < 3; ky++) {
                const float* rowp = xb + ic * 361 + (oy + ky) * 19;
                float rr[19];
#pragma unroll
                for (int j = 0; j < 19; j++) rr[j] = rowp[j];
#pragma unroll
                for (int o = 0; o < 4; o++) {
                    const float* wp = w1 + (ocb + o) * 27 + ic * 9 + ky * 3;
                    float wa = wp[0], wbv = wp[1], wc = wp[2];
#pragma unroll
                    for (int ox = 0; ox < 17; ox++)
                        acc[o][ox] += rr[ox] * wa + rr[ox + 1] * wbv + rr[ox + 2] * wc;
                }
            }
        }
#pragma unroll
        for (int o = 0; o < 4; o++) {
            float* op = c1s + nd * 2312 + (ocb + o) * 289 + oy * 17;
#pragma unroll
            for (int ox = 0; ox < 17; ox++) op[ox] = fmaxf(acc[o][ox], 0.f);
        }
    }
    __syncthreads();

    {
        int icg = t & 3;
        int pid = t >> 2;
        int nd  = pid / 7;
        int oy  = pid - nd * 7;
        bool valid = (nd < nLocal);
        int ndc = valid ? nd : 0;
        const float* ib = c1s + ndc * 2312;

        float acc[35];
#pragma unroll
        for (int j = 0; j < 35; j++) acc[j] = 0.f;

#pragma unroll
        for (int ii = 0; ii < 2; ii++) {
            int ic = icg * 2 + ii;
#pragma unroll
            for (int ky = 0; ky < 5; ky++) {
                const float* rowp = ib + ic * 289 + (oy * 2 + ky) * 17;
                float rr[17];
#pragma unroll
                for (int j = 0; j < 17; j++) rr[j] = rowp[j];
#pragma unroll
                for (int oc = 0; oc < 5; oc++) {
                    const float* wp = w2 + oc * 200 + ic * 25 + ky * 5;
                    float wv[5];
#pragma unroll
                    for (int kx = 0; kx < 5; kx++) wv[kx] = wp[kx];
#pragma unroll
                    for (int ox = 0; ox < 7; ox++) {
#pragma unroll
                        for (int kx = 0; kx < 5; kx++)
                            acc[oc * 7 + ox] += rr[ox * 2 + kx] * wv[kx];
                    }
                }
            }
        }
#pragma unroll
        for (int j = 0; j < 35; j++) {
            acc[j] += __shfl_xor_sync(0xffffffff, acc[j], 1);
            acc[j] += __shfl_xor_sync(0xffffffff, acc[j], 2);
        }
        if (valid && icg == 0) {
            float* fp = g_feat + (size_t)(node0 + nd) * 245 + oy * 7;
#pragma unroll
            for (int oc = 0; oc < 5; oc++) {
                float bias = w2[1000 + oc];
#pragma unroll
                for (int ox = 0; ox < 7; ox++)
                    fp[oc * 49 + ox] = fmaxf(acc[oc * 7 + ox] + bias, 0.f);
            }
        }
    }
}

// ---------------- degree ----------------
__global__ void k_deg(const int* __restrict__ ei, const float* __restrict__ ea, int E) {
    int e = blockIdx.x * blockDim.x + threadIdx.x;
    if (e >= E) return;
    int c = ei[E + e];
    atomicAdd(&g_deg[c], ea[e]);
    atomicAdd(&g_indeg[c], 1);
}

// ---------------- warp-shuffle scan (+ dinv) ----------------
__global__ __launch_bounds__(1024) void k_scan(int n) {
    __shared__ int ws[32];
    __shared__ int s_carry;
    int t = threadIdx.x;
    int lane = t & 31, wid = t >> 5;
    if (t == 0) s_carry = 0;
    __syncthreads();
    for (int base = 0; base < n; base += 1024) {
        int i = base + t;
        int v = (i < n) ? g_indeg[i] : 0;
        if (i < n) {
            float d = g_deg[i];
            g_dinv[i] = (d > 0.f) ? rsqrtf(d) : 0.f;
        }
        int inc = v;
#pragma unroll
        for (int d = 1; d < 32; d <<= 1) {
            int u = __shfl_up_sync(0xffffffffu, inc, d);
            if (lane >= d) inc += u;
        }
        if (lane == 31) ws[wid] = inc;
        __syncthreads();
        if (wid == 0) {
            int s = ws[lane];
#pragma unroll
            for (int d = 1; d < 32; d <<= 1) {
                int u = __shfl_up_sync(0xffffffffu, s, d);
                if (lane >= d) s += u;
            }
            ws[lane] = s;
        }
        __syncthreads();
        int chunkoff = wid ? ws[wid - 1] : 0;
        int carry = s_carry;
        int excl = carry + chunkoff + inc - v;
        if (i < n) { g_off[i] = excl; g_cur[i] = excl; }
        __syncthreads();
        if (t == 0) s_carry = carry + ws[31];
        __syncthreads();
    }
    if (t == 0) g_off[n] = s_carry;
}

// ---------------- CSR build ----------------
__global__ void k_csr(const int* __restrict__ ei, const float* __restrict__ ea, int E) {
    int e = blockIdx.x * blockDim.x + threadIdx.x;
    if (e >= E) return;
    int r = ei[e];
    int c = ei[E + e];
    float nrm = 0.2f * g_dinv[r] * ea[e] * g_dinv[c];
    int pos = atomicAdd(&g_cur[c], 1);
    g_edge[pos] = make_int2(r, __float_as_int(nrm));
}

// ---------------- l1 GEMM -> h0 (fp32 + fp16 mirror) ----------------
__global__ __launch_bounds__(256) void k_l1(const float* __restrict__ l1w,
                                            const float* __restrict__ l1b, int n)
{
    __shared__ float As[16 * 132];
    __shared__ float Bs[16 * 132];
    int t = threadIdx.x;
    int tx = t & 15, ty = t >> 4;
    float acc[8][8];
#pragma unroll
    for (int i = 0; i < 8; i++)
#pragma unroll
        for (int j = 0; j < 8; j++) acc[i][j] = 0.f;

    int rowBase = blockIdx.x * 128;
    for (int k0 = 0; k0 < 245; k0 += 16) {
#pragma unroll
        for (int i = 0; i < 8; i++) {
            int e = t + i * 256;
            int m = e >> 4, kk = e & 15;
            int node = rowBase + m, k = k0 + kk;
            As[kk * 132 + m] = (node < n && k < 245) ? g_feat[(size_t)node * 245 + k] : 0.f;
            Bs[kk * 132 + m] = (k < 245) ? l1w[m * 245 + k] : 0.f;
        }
        __syncthreads();
#pragma unroll
        for (int kk = 0; kk < 16; kk++) {
            const float4* ap = (const float4*)(As + kk * 132 + ty * 8);
            const float4* bp = (const float4*)(Bs + kk * 132 + tx * 8);
            float4 a0 = ap[0], a1 = ap[1];
            float4 b0 = bp[0], b1 = bp[1];
            float a[8] = {a0.x, a0.y, a0.z, a0.w, a1.x, a1.y, a1.z, a1.w};
            float b[8] = {b0.x, b0.y, b0.z, b0.w, b1.x, b1.y, b1.z, b1.w};
#pragma unroll
            for (int i = 0; i < 8; i++)
#pragma unroll
                for (int j = 0; j < 8; j++) acc[i][j] += a[i] * b[j];
        }
        __syncthreads();
    }
    float4 lb0 = ((const float4*)l1b)[tx * 2];
    float4 lb1 = ((const float4*)l1b)[tx * 2 + 1];
    float lb[8] = {lb0.x, lb0.y, lb0.z, lb0.w, lb1.x, lb1.y, lb1.z, lb1.w};
#pragma unroll
    for (int i = 0; i < 8; i++) {
        int node = rowBase + ty * 8 + i;
        if (node >= n) continue;
        float o[8];
#pragma unroll
        for (int j = 0; j < 8; j++) o[j] = fmaxf(acc[i][j] + lb[j], 0.f);
        float4* op = (float4*)(g_h0 + (size_t)node * 128 + tx * 8);
        op[0] = make_float4(o[0], o[1], o[2], o[3]);
        op[1] = make_float4(o[4], o[5], o[6], o[7]);
        __half2 p0 = __floats2half2_rn(o[0], o[1]);
        __half2 p1 = __floats2half2_rn(o[2], o[3]);
        __half2 p2 = __floats2half2_rn(o[4], o[5]);
        __half2 p3 = __floats2half2_rn(o[6], o[7]);
        __half2* hp = g_h0h + (size_t)node * 64 + tx * 4;
        hp[0] = p0; hp[1] = p1; hp[2] = p2; hp[3] = p3;
    }
}

// ---------------- APPNP hop: fp16 gather, fp32 accumulate; hop2 fuses BN -------
__global__ __launch_bounds__(256) void k_hop(int which, int n) {
    __shared__ float ssum[128], ssq[128];
    int t = threadIdx.x;
    if (which) {
        if (t < 128) { ssum[t] = 0.f; ssq[t] = 0.f; }
        __syncthreads();
    }
    int wid = (blockIdx.x * 256 + t) >> 5;
    int lane = t & 31;
    bool valid = (wid < n);

    float4 o = make_float4(0.f, 0.f, 0.f, 0.f);
    if (valid) {
        const __half2* hin = which ? g_h1h : g_h0h;
        int off0 = g_off[wid], off1 = g_off[wid + 1];

        float a0 = 0.f, a1 = 0.f, a2 = 0.f, a3 = 0.f;
        int e = off0;
        for (; e + 2 <= off1; e += 2) {
            int2 ra = g_edge[e];
            int2 rb = g_edge[e + 1];
            uint2 ua = *(const uint2*)(hin + (size_t)ra.x * 64 + lane * 2);
            uint2 ub = *(const uint2*)(hin + (size_t)rb.x * 64 + lane * 2);
            float w0 = __int_as_float(ra.y);
            float w1 = __int_as_float(rb.y);
            float2 fa0 = __half22float2(*(const __half2*)&ua.x);
            float2 fa1 = __half22float2(*(const __half2*)&ua.y);
            float2 fb0 = __half22float2(*(const __half2*)&ub.x);
            float2 fb1 = __half22float2(*(const __half2*)&ub.y);
            a0 += w0 * fa0.x; a1 += w0 * fa0.y; a2 += w0 * fa1.x; a3 += w0 * fa1.y;
            a0 += w1 * fb0.x; a1 += w1 * fb0.y; a2 += w1 * fb1.x; a3 += w1 * fb1.y;
        }
        if (e < off1) {
            int2 ra = g_edge[e];
            uint2 ua = *(const uint2*)(hin + (size_t)ra.x * 64 + lane * 2);
            float w0 = __int_as_float(ra.y);
            float2 fa0 = __half22float2(*(const __half2*)&ua.x);
            float2 fa1 = __half22float2(*(const __half2*)&ua.y);
            a0 += w0 * fa0.x; a1 += w0 * fa0.y; a2 += w0 * fa1.x; a3 += w0 * fa1.y;
        }
        float4 h0v = ((const float4*)g_h0)[(size_t)wid * 32 + lane];
        o.x = a0 + 0.8f * h0v.x;
        o.y = a1 + 0.8f * h0v.y;
        o.z = a2 + 0.8f * h0v.z;
        o.w = a3 + 0.8f * h0v.w;
        if (which) {
            ((float4*)g_h2)[(size_t)wid * 32 + lane] = o;
        } else {
            ((float4*)g_h1)[(size_t)wid * 32 + lane] = o;
            __half2 p0 = __floats2half2_rn(o.x, o.y);
            __half2 p1 = __floats2half2_rn(o.z, o.w);
            __half2* hp = g_h1h + (size_t)wid * 64 + lane * 2;
            hp[0] = p0; hp[1] = p1;
        }
    }
    if (which) {
        if (valid) {
            int c = lane * 4;
            atomicAdd(&ssum[c + 0], o.x); atomicAdd(&ssq[c + 0], o.x * o.x);
            atomicAdd(&ssum[c + 1], o.y); atomicAdd(&ssq[c + 1], o.y * o.y);
            atomicAdd(&ssum[c + 2], o.z); atomicAdd(&ssq[c + 2], o.z * o.z);
            atomicAdd(&ssum[c + 3], o.w); atomicAdd(&ssq[c + 3], o.w * o.w);
        }
        __syncthreads();
        if (t < 128) {
            atomicAdd(&g_bnsum[t], ssum[t]);
            atomicAdd(&g_bnsq[t], ssq[t]);
        }
    }
}

__global__ void k_bnfin(const float* __restrict__ gamma, const float* __restrict__ beta,
                        float invN) {
    int c = threadIdx.x;
    float mean = g_bnsum[c] * invN;
    float var = g_bnsq[c] * invN - mean * mean;
    float inv = rsqrtf(var + 1e-5f);
    float a = gamma[c] * inv;
    g_ab[c] = a;
    g_ab[128 + c] = beta[c] - mean * a;
}

// ---------------- normalize + write node_x + pool scatter ----------------
__global__ void k_pool(const int* __restrict__ batch, float* __restrict__ out, int n) {
    int idx = blockIdx.x * blockDim.x + threadIdx.x;
    if (idx >= n * 32) return;
    int node = idx >> 5, q = idx & 31;
    int c = q * 4;
    float4 v = ((const float4*)g_h2)[idx];
    float4 r;
    r.x = v.x * g_ab[c + 0] + g_ab[128 + c + 0];
    r.y = v.y * g_ab[c + 1] + g_ab[128 + c + 1];
    r.z = v.z * g_ab[c + 2] + g_ab[128 + c + 2];
    r.w = v.w * g_ab[c + 3] + g_ab[128 + c + 3];
    ((float4*)out)[640 + idx] = r;
    int g = batch[node];
    float* gp = g_gsum + (size_t)g * 128 + c;
    atomicAdd(gp + 0, r.x);
    atomicAdd(gp + 1, r.y);
    atomicAdd(gp + 2, r.z);
    atomicAdd(gp + 3, r.w);
}

__global__ void k_gcnt(const int* __restrict__ batch, int n) {
    int i = blockIdx.x * blockDim.x + threadIdx.x;
    if (i >= n) return;
    atomicAdd(&g_gcnt[batch[i]], 1.0f);
}

// ---------------- graph MLP classifier ----------------
__global__ __launch_bounds__(64) void k_mlp(const float* __restrict__ l2w,
                                            const float* __restrict__ l2b,
                                            const float* __restrict__ l3w,
                                            const float* __restrict__ l3b,
                                            float* __restrict__ out) {
    int g = blockIdx.x, t = threadIdx.x;
    __shared__ float gx[128], hid[64];
    float cnt = fmaxf(g_gcnt[g], 1.f);
    float ic = 1.f / cnt;
    gx[t]      = g_gsum[(size_t)g * 128 + t] * ic;
    gx[t + 64] = g_gsum[(size_t)g * 128 + 64 + t] * ic;
    __syncthreads();
    float s = l2b[t];
    const float* wr = l2w + t * 128;
#pragma unroll 8
    for (int c = 0; c < 128; c++) s += gx[c] * wr[c];
    hid[t] = fmaxf(s, 0.f);
    __syncthreads();
    if (t < 5) {
        float s2 = l3b[t];
        const float* wr3 = l3w + t * 64;
#pragma unroll 8
        for (int j = 0; j < 64; j++) s2 += hid[j] * wr3[j];
        out[g * 5 + t] = s2;
    }
}

// ---------------- launcher (two-stream fork/join, graph-capturable) -----------
extern "C" void kernel_launch(void* const* d_in, const int* in_sizes, int n_in,
                              void* d_out, int out_size) {
    static cudaStream_t sB = nullptr;
    static cudaEvent_t evFork = nullptr, evJoin = nullptr;
    if (sB == nullptr) {
        cudaStreamCreateWithFlags(&sB, cudaStreamNonBlocking);
        cudaEventCreateWithFlags(&evFork, cudaEventDisableTiming);
        cudaEventCreateWithFlags(&evJoin, cudaEventDisableTiming);
    }

    int wb = (n_in > 4 && in_sizes[4] == 216) ? 4 : 5;

    const float* x     = (const float*)d_in[0];
    const int*   ei    = (const int*)d_in[1];
    const float* ea    = (const float*)d_in[2];
    const int*   batch = (const int*)d_in[3];
    const float* c1w = (const float*)d_in[wb + 0];
    const float* c1b = (const float*)d_in[wb + 1];
    const float* c2w = (const float*)d_in[wb + 2];
    const float* c2b = (const float*)d_in[wb + 3];
    const float* l1w = (const float*)d_in[wb + 4];
    const float* l1b = (const float*)d_in[wb + 5];
    const float* gam = (const float*)d_in[wb + 6];
    const float* bet = (const float*)d_in[wb + 7];
    const float* l2w = (const float*)d_in[wb + 8];
    const float* l2b = (const float*)d_in[wb + 9];
    const float* l3w = (const float*)d_in[wb + 10];
    const float* l3b = (const float*)d_in[wb + 11];

    int n = in_sizes[0] / 1083;
    int E = in_sizes[1] / 2;
    int G = (out_size - n * 128) / 5;
    float* out = (float*)d_out;

    int cnnSmem = CNN_SMEM_FLOATS * 4;
    cudaFuncSetAttribute(k_cnn, cudaFuncAttributeMaxDynamicSharedMemorySize, cnnSmem);

    // stream 0: zero, then fork
    k_zero<<<(GMAXG * 128 + 255) / 256, 256>>>(n);
    cudaEventRecord(evFork, 0);
    cudaStreamWaitEvent(sB, evFork, 0);

    // stream B: edge preprocessing chain (independent of CNN path)
    k_deg<<<(E + 255) / 256, 256, 0, sB>>>(ei, ea, E);
    k_scan<<<1, 1024, 0, sB>>>(n);
    k_csr<<<(E + 255) / 256, 256, 0, sB>>>(ei, ea, E);
    k_gcnt<<<(n + 255) / 256, 256, 0, sB>>>(batch, n);
    cudaEventRecord(evJoin, sB);

    // stream 0: node encoder path (overlaps with stream B)
    k_cnn<<<(n + CNN_NPB - 1) / CNN_NPB, 256, cnnSmem>>>(x, c1w, c1b, c2w, c2b, n);
    k_l1<<<(n + 127) / 128, 256>>>(l1w, l1b, n);

    // join, then the dependent tail
    cudaStreamWaitEvent(0, evJoin, 0);
    int hopBlocks = (n * 32 + 255) / 256;
    k_hop<<<hopBlocks, 256>>>(0, n);
    k_hop<<<hopBlocks, 256>>>(1, n);   // fused BN stats

    k_bnfin<<<1, 128>>>(gam, bet, 1.0f / (float)n);
    k_pool<<<(n * 32 + 255) / 256, 256>>>(batch, out, n);
    k_mlp<<<G, 64>>>(l2w, l2b, l3w, l3b, out);
}